// round 5
// baseline (speedup 1.0000x reference)
#include <cuda_runtime.h>
#include <cuda_fp16.h>
#include <math.h>
#include <stdint.h>

#define S_   256
#define B_   512
#define H_   512
#define E_   256
#define L_   4
#define OUT_ 128

// ---------------- scratch (no allocs allowed) ----------------
__device__ float g_Wh[B_ * H_];
__device__ float g_rnn[B_ * (H_ + E_)];
__device__ float g_energy[S_ * B_];
__device__ float g_gi[B_ * 3 * H_];
__device__ float g_gh[B_ * 3 * H_];

// ---------------- helpers ----------------
__device__ __forceinline__ uint32_t smem_u32(const void* p) {
    uint32_t a;
    asm("{ .reg .u64 t; cvta.to.shared.u64 t, %1; cvt.u32.u64 %0, t; }" : "=r"(a) : "l"(p));
    return a;
}

__device__ __forceinline__ void ldsm4(uint32_t* r, uint32_t addr) {
    asm volatile("ldmatrix.sync.aligned.m8n8.x4.shared.b16 {%0,%1,%2,%3}, [%4];"
                 : "=r"(r[0]), "=r"(r[1]), "=r"(r[2]), "=r"(r[3]) : "r"(addr));
}

__device__ __forceinline__ void mma16816(float* c, const uint32_t* a, uint32_t b0, uint32_t b1) {
    asm volatile(
        "mma.sync.aligned.m16n8k16.row.col.f32.f16.f16.f32 "
        "{%0,%1,%2,%3}, {%4,%5,%6,%7}, {%8,%9}, {%0,%1,%2,%3};\n"
        : "+f"(c[0]), "+f"(c[1]), "+f"(c[2]), "+f"(c[3])
        : "r"(a[0]), "r"(a[1]), "r"(a[2]), "r"(a[3]), "r"(b0), "r"(b1));
}

// gmem -> regs: N_ float4 per thread, rows of a [*,K] row-major matrix, k-chunk kt*16
template<int N_, int THREADS>
__device__ __forceinline__ void ldg_tile(float4* r, const float* __restrict__ base,
                                         int row0, int K, int kt, int tid) {
#pragma unroll
    for (int i = 0; i < N_; i++) {
        int idx = i * THREADS + tid;
        r[i] = *(const float4*)&base[(size_t)(row0 + (idx >> 2)) * K + kt * 16 + (idx & 3) * 4];
    }
}

// regs -> smem (fp16, 48B-strided rows: 16 halves data + 8 pad)
template<int N_, int THREADS>
__device__ __forceinline__ void sts_tile(const float4* r, __half* dst, int tid) {
#pragma unroll
    for (int i = 0; i < N_; i++) {
        int idx = i * THREADS + tid;
        __half2* d = (__half2*)(dst + (idx >> 2) * 24 + (idx & 3) * 4);
        d[0] = __float22half2_rn(make_float2(r[i].x, r[i].y));
        d[1] = __float22half2_rn(make_float2(r[i].z, r[i].w));
    }
}

// ---------------- fp16 GEMM mainloop, warp tile 64x32 ----------------
// Block tile BM x BN, warps = (BM/64)*(BN/32), double-buffered smem + reg prefetch.
template<int BM, int BN>
__device__ __forceinline__ void hgemm_loop32(float acc[4][4][4],
                                             const float* __restrict__ A,
                                             const float* __restrict__ W,
                                             int row0, int n0, int K,
                                             __half* sA, __half* sW) {
    constexpr int THREADS = (BM / 64) * (BN / 32) * 32;
    constexpr int NA = (BM * 4) / THREADS;
    constexpr int NB = (BN * 4) / THREADS;
    constexpr int WN = BN / 32;

    const int tid = threadIdx.x;
    const int lane = tid & 31, wid = tid >> 5;
    const int wm = wid / WN, wn = wid % WN;
    const int lr = (lane & 7) + ((lane >> 3) & 1) * 8;  // row within 16-row tile
    const int lb = ((lane >> 4) & 1) * 16;              // byte offset (k half)
    const uint32_t aBase = smem_u32(sA);
    const uint32_t wBase = smem_u32(sW);

    float4 ra[NA], rw[NB];
    ldg_tile<NA, THREADS>(ra, A, row0, K, 0, tid);
    ldg_tile<NB, THREADS>(rw, W, n0, K, 0, tid);
    sts_tile<NA, THREADS>(ra, sA, tid);
    sts_tile<NB, THREADS>(rw, sW, tid);
    __syncthreads();

    const int nk = K / 16;
    for (int kt = 0; kt < nk; kt++) {
        const int p = kt & 1;
        if (kt + 1 < nk) {
            ldg_tile<NA, THREADS>(ra, A, row0, K, kt + 1, tid);
            ldg_tile<NB, THREADS>(rw, W, n0, K, kt + 1, tid);
        }
        const uint32_t aOff = aBase + (uint32_t)p * BM * 48;
        const uint32_t wOff = wBase + (uint32_t)p * BN * 48;
        uint32_t af[4][4], bt[2][4];
#pragma unroll
        for (int mi = 0; mi < 4; mi++)
            ldsm4(af[mi], aOff + (uint32_t)(wm * 64 + mi * 16 + lr) * 48 + lb);
#pragma unroll
        for (int nt = 0; nt < 2; nt++)
            ldsm4(bt[nt], wOff + (uint32_t)(wn * 32 + nt * 16 + lr) * 48 + lb);
#pragma unroll
        for (int mi = 0; mi < 4; mi++)
#pragma unroll
            for (int ni = 0; ni < 4; ni++) {
                const int nt = ni >> 1, sub = ni & 1;
                mma16816(acc[mi][ni], af[mi], bt[nt][sub ? 1 : 0], bt[nt][sub ? 3 : 2]);
            }
        if (kt + 1 < nk) {
            sts_tile<NA, THREADS>(ra, sA + (p ^ 1) * BM * 24, tid);
            sts_tile<NB, THREADS>(rw, sW + (p ^ 1) * BN * 24, tid);
        }
        __syncthreads();
    }
}

// ---------------- fused energy kernel (512 threads, 16 warps) ----------------
// energy[r] = ab + sum_o aw[o]*tanh( Es[r,:]@Uw[o,:] + Ub[o] + Wh[r&511, o] )
__global__ void __launch_bounds__(512, 1) energy_hmma_kernel(
    const float* __restrict__ Es, const float* __restrict__ Uw,
    const float* __restrict__ Ub, const float* __restrict__ Wh,
    const float* __restrict__ aw, const float* __restrict__ ab,
    float* __restrict__ energy) {
    __shared__ __align__(16) __half sA[2 * 128 * 24];
    __shared__ __align__(16) __half sW[2 * 256 * 24];
    __shared__ float esum[128];

    const int tid = threadIdx.x;
    const int lane = tid & 31, wid = tid >> 5;
    const int wm = wid >> 3, wn = wid & 7;   // 2 x 8 warp grid, warp tile 64x32
    const int g = lane >> 2, tg = lane & 3;
    const int r0 = blockIdx.x * 128;
    const int b0 = r0 & (B_ - 1);

    if (tid < 128) esum[tid] = 0.f;

    for (int nc = 0; nc < 2; nc++) {
        float acc[4][4][4] = {};
        hgemm_loop32<128, 256>(acc, Es, Uw, r0, nc * 256, H_, sA, sW);

#pragma unroll
        for (int mi = 0; mi < 4; mi++)
#pragma unroll
            for (int hf = 0; hf < 2; hf++) {
                const int rl = wm * 64 + mi * 16 + g + hf * 8;
                const float* WhR = Wh + (size_t)(b0 + rl) * H_;
                float s = 0.f;
#pragma unroll
                for (int ni = 0; ni < 4; ni++) {
                    const int col = nc * 256 + wn * 32 + ni * 8 + tg * 2;
                    float v0 = acc[mi][ni][hf * 2 + 0] + Ub[col] + WhR[col];
                    float v1 = acc[mi][ni][hf * 2 + 1] + Ub[col + 1] + WhR[col + 1];
                    s += tanhf(v0) * aw[col] + tanhf(v1) * aw[col + 1];
                }
                s += __shfl_xor_sync(0xffffffffu, s, 1);
                s += __shfl_xor_sync(0xffffffffu, s, 2);
                if (tg == 0) atomicAdd(&esum[rl], s);
            }
    }
    __syncthreads();
    if (tid < 128) energy[r0 + tid] = esum[tid] + ab[0];
}

// ---------------- generic fp16 GEMM (+bias), 2 jobs via gridDim.z ----------------
template<int BM, int BN>
__global__ void __launch_bounds__((BM / 64) * (BN / 32) * 32, 1) hgemm2_kernel(
    const float* __restrict__ A0, const float* __restrict__ W0,
    const float* __restrict__ bias0, float* __restrict__ C0, int K0,
    const float* __restrict__ A1, const float* __restrict__ W1,
    const float* __restrict__ bias1, float* __restrict__ C1, int K1,
    int N) {
    __shared__ __align__(16) __half sA[2 * BM * 24];
    __shared__ __align__(16) __half sW[2 * BN * 24];

    const float *A, *W, *bias;
    float* C;
    int K;
    if (blockIdx.z == 0) { A = A0; W = W0; bias = bias0; C = C0; K = K0; }
    else                 { A = A1; W = W1; bias = bias1; C = C1; K = K1; }

    const int tid = threadIdx.x;
    const int lane = tid & 31, wid = tid >> 5;
    constexpr int WN = BN / 32;
    const int wm = wid / WN, wn = wid % WN;
    const int g = lane >> 2, tg = lane & 3;
    const int m0 = blockIdx.y * BM;
    const int n0 = blockIdx.x * BN;

    float acc[4][4][4] = {};
    hgemm_loop32<BM, BN>(acc, A, W, m0, n0, K, sA, sW);

#pragma unroll
    for (int mi = 0; mi < 4; mi++)
#pragma unroll
        for (int hf = 0; hf < 2; hf++) {
            const int row = m0 + wm * 64 + mi * 16 + g + hf * 8;
#pragma unroll
            for (int ni = 0; ni < 4; ni++) {
                const int col = n0 + wn * 32 + ni * 8 + tg * 2;
                float2 o;
                o.x = acc[mi][ni][hf * 2 + 0] + bias[col];
                o.y = acc[mi][ni][hf * 2 + 1] + bias[col + 1];
                *(float2*)&C[(size_t)row * N + col] = o;
            }
        }
}

// ---------------- fused softmax + context + embedding (one block per b) ----------------
__global__ void __launch_bounds__(256) attn_ctx_kernel(
    const float* __restrict__ energy, const float* __restrict__ Es,
    const int* __restrict__ x, const float* __restrict__ emb,
    float* __restrict__ rnn) {
    __shared__ float red[S_];
    __shared__ float att[S_];
    const int b = blockIdx.x;
    const int s = threadIdx.x;

    float v = energy[s * B_ + b];
    red[s] = v;
    __syncthreads();
    for (int off = S_ / 2; off; off >>= 1) {
        if (s < off) red[s] = fmaxf(red[s], red[s + off]);
        __syncthreads();
    }
    float m = red[0];
    __syncthreads();
    float ex = __expf(v - m);
    red[s] = ex;
    __syncthreads();
    for (int off = S_ / 2; off; off >>= 1) {
        if (s < off) red[s] += red[s + off];
        __syncthreads();
    }
    att[s] = ex / red[0];
    __syncthreads();

    // context: each thread owns 2 consecutive h (float2)
    const int h = s * 2;
    float cx = 0.f, cy = 0.f;
    const float* base = Es + (size_t)b * H_ + h;
#pragma unroll 4
    for (int s2 = 0; s2 < S_; s2++) {
        float a = att[s2];
        float2 e = *(const float2*)&base[(size_t)s2 * B_ * H_];
        cx = fmaf(a, e.x, cx);
        cy = fmaf(a, e.y, cy);
    }
    *(float2*)&rnn[(size_t)b * (H_ + E_) + h] = make_float2(cx, cy);

    // embedding gather (E_ == 256 == blockDim)
    rnn[(size_t)b * (H_ + E_) + H_ + s] = emb[(size_t)x[b] * E_ + s];
}

// ---------------- GRU gate fusion ----------------
__global__ void gate_kernel(const float* __restrict__ gi,
                            const float* __restrict__ gh,
                            const float* __restrict__ hprev,
                            float* __restrict__ hnew) {
    const int idx = blockIdx.x * 256 + threadIdx.x;
    const int b = idx >> 9;
    const int o = idx & (H_ - 1);
    const float* gib = gi + (size_t)b * 3 * H_;
    const float* ghb = gh + (size_t)b * 3 * H_;
    float ir = gib[o], iz = gib[o + H_], inn = gib[o + 2 * H_];
    float hr = ghb[o], hz = ghb[o + H_], hn = ghb[o + 2 * H_];
    float r = 1.f / (1.f + __expf(-(ir + hr)));
    float z = 1.f / (1.f + __expf(-(iz + hz)));
    float n = tanhf(fmaf(r, hn, inn));
    float h = hprev[idx];
    hnew[idx] = fmaf(z, h - n, n);
}

// ---------------- launch ----------------
extern "C" void kernel_launch(void* const* d_in, const int* in_sizes, int n_in,
                              void* d_out, int out_size) {
    const int*   x      = (const int*)  d_in[0];
    const float* Es     = (const float*)d_in[1];
    const float* hidden = (const float*)d_in[2];
    const float* emb    = (const float*)d_in[4];
    const float* Uw     = (const float*)d_in[5];
    const float* Ub     = (const float*)d_in[6];
    const float* Ww     = (const float*)d_in[7];
    const float* Wb     = (const float*)d_in[8];
    const float* aw     = (const float*)d_in[9];
    const float* ab     = (const float*)d_in[10];
    const float* w_ih0  = (const float*)d_in[11];
    const float* w_hh0  = (const float*)d_in[12];
    const float* b_ih0  = (const float*)d_in[13];
    const float* b_hh0  = (const float*)d_in[14];
    const float* w_ih_r = (const float*)d_in[15];
    const float* w_hh_r = (const float*)d_in[16];
    const float* b_ih_r = (const float*)d_in[17];
    const float* b_hh_r = (const float*)d_in[18];
    const float* fcw    = (const float*)d_in[19];
    const float* fcb    = (const float*)d_in[20];

    float* out     = (float*)d_out;
    float* pred    = out;               // [B, OUT]
    float* hid_out = out + B_ * OUT_;   // [L, B, H]

    float *Wh, *rnn, *energy, *gi, *gh;
    cudaGetSymbolAddress((void**)&Wh,     g_Wh);
    cudaGetSymbolAddress((void**)&rnn,    g_rnn);
    cudaGetSymbolAddress((void**)&energy, g_energy);
    cudaGetSymbolAddress((void**)&gi,     g_gi);
    cudaGetSymbolAddress((void**)&gh,     g_gh);

    const float* hlast = hidden + (size_t)(L_ - 1) * B_ * H_;

    // 1) Wh = hidden[-1] @ Ww^T + Wb   [512x512x512]
    hgemm2_kernel<128, 128><<<dim3(H_ / 128, B_ / 128, 1), 256>>>(
        hlast, Ww, Wb, Wh, H_, hlast, Ww, Wb, Wh, H_, H_);

    // 2) fused energy (fp16 tensor-core GEMM + tanh + aw-reduction)
    energy_hmma_kernel<<<(S_ * B_) / 128, 512>>>(Es, Uw, Ub, Wh, aw, ab, energy);

    // 3) softmax + context + embedding, one launch
    attn_ctx_kernel<<<B_, 256>>>(energy, Es, x, emb, rnn);

    // 4) GRU layer 0: gi and gh in one launch (gridDim.z = 2)
    hgemm2_kernel<128, 128><<<dim3(3 * H_ / 128, B_ / 128, 2), 256>>>(
        rnn, w_ih0, b_ih0, gi, H_ + E_,
        hidden, w_hh0, b_hh0, gh, H_,
        3 * H_);
    gate_kernel<<<(B_ * H_) / 256, 256>>>(gi, gh, hidden, hid_out);

    // 5) GRU layers 1..3
    for (int l = 1; l < L_; l++) {
        const float* wih = w_ih_r + (size_t)(l - 1) * 3 * H_ * H_;
        const float* whh = w_hh_r + (size_t)(l - 1) * 3 * H_ * H_;
        const float* bih = b_ih_r + (size_t)(l - 1) * 3 * H_;
        const float* bhh = b_hh_r + (size_t)(l - 1) * 3 * H_;
        const float* hin = hid_out + (size_t)(l - 1) * B_ * H_;
        const float* hpv = hidden + (size_t)l * B_ * H_;
        hgemm2_kernel<128, 128><<<dim3(3 * H_ / 128, B_ / 128, 2), 256>>>(
            hin, wih, bih, gi, H_,
            hpv, whh, bhh, gh, H_,
            3 * H_);
        gate_kernel<<<(B_ * H_) / 256, 256>>>(gi, gh, hpv, hid_out + (size_t)l * B_ * H_);
    }

    // 6) predictions = h_last @ fcw^T + fcb   [512x128x512]
    hgemm2_kernel<128, 128><<<dim3(OUT_ / 128, B_ / 128, 1), 256>>>(
        hid_out + (size_t)(L_ - 1) * B_ * H_, fcw, fcb, pred, H_,
        hid_out + (size_t)(L_ - 1) * B_ * H_, fcw, fcb, pred, H_,
        OUT_);
}

// round 7
// speedup vs baseline: 1.0317x; 1.0317x over previous
#include <cuda_runtime.h>
#include <cuda_fp16.h>
#include <math.h>
#include <stdint.h>

#define S_   256
#define B_   512
#define H_   512
#define E_   256
#define L_   4
#define OUT_ 128

// ---------------- scratch (no allocs allowed) ----------------
__device__ float g_Wh[B_ * H_];
__device__ float g_rnn[B_ * (H_ + E_)];
__device__ float g_energy[S_ * B_];

// ---------------- helpers ----------------
__device__ __forceinline__ uint32_t smem_u32(const void* p) {
    uint32_t a;
    asm("{ .reg .u64 t; cvta.to.shared.u64 t, %1; cvt.u32.u64 %0, t; }" : "=r"(a) : "l"(p));
    return a;
}

__device__ __forceinline__ void ldsm4(uint32_t* r, uint32_t addr) {
    asm volatile("ldmatrix.sync.aligned.m8n8.x4.shared.b16 {%0,%1,%2,%3}, [%4];"
                 : "=r"(r[0]), "=r"(r[1]), "=r"(r[2]), "=r"(r[3]) : "r"(addr));
}

__device__ __forceinline__ void mma16816(float* c, const uint32_t* a, uint32_t b0, uint32_t b1) {
    asm volatile(
        "mma.sync.aligned.m16n8k16.row.col.f32.f16.f16.f32 "
        "{%0,%1,%2,%3}, {%4,%5,%6,%7}, {%8,%9}, {%0,%1,%2,%3};\n"
        : "+f"(c[0]), "+f"(c[1]), "+f"(c[2]), "+f"(c[3])
        : "r"(a[0]), "r"(a[1]), "r"(a[2]), "r"(a[3]), "r"(b0), "r"(b1));
}

__device__ __forceinline__ void sts16(__half* dst, float4 v) {
    __half2* d = (__half2*)dst;
    d[0] = __float22half2_rn(make_float2(v.x, v.y));
    d[1] = __float22half2_rn(make_float2(v.z, v.w));
}

__device__ __forceinline__ float sigf(float x) { return 1.f / (1.f + __expf(-x)); }

// gmem -> regs: N_ float4 per thread (energy path)
template<int N_, int THREADS>
__device__ __forceinline__ void ldg_tile(float4* r, const float* __restrict__ base,
                                         int row0, int K, int kt, int tid) {
#pragma unroll
    for (int i = 0; i < N_; i++) {
        int idx = i * THREADS + tid;
        r[i] = *(const float4*)&base[(size_t)(row0 + (idx >> 2)) * K + kt * 16 + (idx & 3) * 4];
    }
}
template<int N_, int THREADS>
__device__ __forceinline__ void sts_tile(const float4* r, __half* dst, int tid) {
#pragma unroll
    for (int i = 0; i < N_; i++) {
        int idx = i * THREADS + tid;
        sts16(dst + (idx >> 2) * 24 + (idx & 3) * 4, r[i]);
    }
}

// ---------------- energy mainloop (warp tile 64x32) ----------------
template<int BM, int BN>
__device__ __forceinline__ void hgemm_loop32(float acc[4][4][4],
                                             const float* __restrict__ A,
                                             const float* __restrict__ W,
                                             int row0, int n0, int K,
                                             __half* sA, __half* sW) {
    constexpr int THREADS = (BM / 64) * (BN / 32) * 32;
    constexpr int NA = (BM * 4) / THREADS;
    constexpr int NB = (BN * 4) / THREADS;
    constexpr int WN = BN / 32;

    const int tid = threadIdx.x;
    const int lane = tid & 31, wid = tid >> 5;
    const int wm = wid / WN, wn = wid % WN;
    const int lr = (lane & 7) + ((lane >> 3) & 1) * 8;
    const int lb = ((lane >> 4) & 1) * 16;
    const uint32_t aBase = smem_u32(sA);
    const uint32_t wBase = smem_u32(sW);

    float4 ra[NA], rw[NB];
    ldg_tile<NA, THREADS>(ra, A, row0, K, 0, tid);
    ldg_tile<NB, THREADS>(rw, W, n0, K, 0, tid);
    sts_tile<NA, THREADS>(ra, sA, tid);
    sts_tile<NB, THREADS>(rw, sW, tid);
    __syncthreads();

    const int nk = K / 16;
    for (int kt = 0; kt < nk; kt++) {
        const int p = kt & 1;
        if (kt + 1 < nk) {
            ldg_tile<NA, THREADS>(ra, A, row0, K, kt + 1, tid);
            ldg_tile<NB, THREADS>(rw, W, n0, K, kt + 1, tid);
        }
        const uint32_t aOff = aBase + (uint32_t)p * BM * 48;
        const uint32_t wOff = wBase + (uint32_t)p * BN * 48;
        uint32_t af[4][4], bt[2][4];
#pragma unroll
        for (int mi = 0; mi < 4; mi++)
            ldsm4(af[mi], aOff + (uint32_t)(wm * 64 + mi * 16 + lr) * 48 + lb);
#pragma unroll
        for (int nt = 0; nt < 2; nt++)
            ldsm4(bt[nt], wOff + (uint32_t)(wn * 32 + nt * 16 + lr) * 48 + lb);
#pragma unroll
        for (int mi = 0; mi < 4; mi++)
#pragma unroll
            for (int ni = 0; ni < 4; ni++) {
                const int nt = ni >> 1, sub = ni & 1;
                mma16816(acc[mi][ni], af[mi], bt[nt][sub ? 1 : 0], bt[nt][sub ? 3 : 2]);
            }
        if (kt + 1 < nk) {
            sts_tile<NA, THREADS>(ra, sA + (p ^ 1) * BM * 24, tid);
            sts_tile<NB, THREADS>(rw, sW + (p ^ 1) * BN * 24, tid);
        }
        __syncthreads();
    }
}

// ---------------- fused energy kernel ----------------
__global__ void __launch_bounds__(512, 1) energy_hmma_kernel(
    const float* __restrict__ Es, const float* __restrict__ Uw,
    const float* __restrict__ Ub, const float* __restrict__ Wh,
    const float* __restrict__ aw, const float* __restrict__ ab,
    float* __restrict__ energy) {
    __shared__ __align__(16) __half sA[2 * 128 * 24];
    __shared__ __align__(16) __half sW[2 * 256 * 24];
    __shared__ float esum[128];

    const int tid = threadIdx.x;
    const int lane = tid & 31, wid = tid >> 5;
    const int wm = wid >> 3, wn = wid & 7;
    const int g = lane >> 2, tg = lane & 3;
    const int r0 = blockIdx.x * 128;
    const int b0 = r0 & (B_ - 1);

    if (tid < 128) esum[tid] = 0.f;

    for (int nc = 0; nc < 2; nc++) {
        float acc[4][4][4] = {};
        hgemm_loop32<128, 256>(acc, Es, Uw, r0, nc * 256, H_, sA, sW);

#pragma unroll
        for (int mi = 0; mi < 4; mi++)
#pragma unroll
            for (int hf = 0; hf < 2; hf++) {
                const int rl = wm * 64 + mi * 16 + g + hf * 8;
                const float* WhR = Wh + (size_t)(b0 + rl) * H_;
                float s = 0.f;
#pragma unroll
                for (int ni = 0; ni < 4; ni++) {
                    const int col = nc * 256 + wn * 32 + ni * 8 + tg * 2;
                    float v0 = acc[mi][ni][hf * 2 + 0] + Ub[col] + WhR[col];
                    float v1 = acc[mi][ni][hf * 2 + 1] + Ub[col + 1] + WhR[col + 1];
                    s += tanhf(v0) * aw[col] + tanhf(v1) * aw[col + 1];
                }
                s += __shfl_xor_sync(0xffffffffu, s, 1);
                s += __shfl_xor_sync(0xffffffffu, s, 2);
                if (tg == 0) atomicAdd(&esum[rl], s);
            }
    }
    __syncthreads();
    if (tid < 128) energy[r0 + tid] = esum[tid] + ab[0];
}

// ---------------- small GEMM: C[M,N] = A@W^T + bias, BM=64 BN=64, 256 thr ----------------
// warps 4m x 2n, warp tile 16x32
__global__ void __launch_bounds__(256, 2) sgemm64_kernel(
    const float* __restrict__ A, const float* __restrict__ W,
    const float* __restrict__ bias, float* __restrict__ C, int K, int N) {
    __shared__ __align__(16) __half sm[2 * 128 * 24];

    const int tid = threadIdx.x;
    const int lane = tid & 31, wid = tid >> 5;
    const int wm = wid >> 1, wn = wid & 1;
    const int g = lane >> 2, tg = lane & 3;
    const int lr = (lane & 7) + ((lane >> 3) & 1) * 8;
    const int lb = ((lane >> 4) & 1) * 16;
    const int m0 = blockIdx.y * 64, n0 = blockIdx.x * 64;
    const uint32_t base = smem_u32(sm);

    const int r = tid >> 2, c = (tid & 3) * 4;
    float acc[4][4] = {};
    float4 ra, rw;
    ra = *(const float4*)&A[(size_t)(m0 + r) * K + c];
    rw = *(const float4*)&W[(size_t)(n0 + r) * K + c];
    sts16(sm + r * 24 + c, ra);
    sts16(sm + (64 + r) * 24 + c, rw);
    __syncthreads();

    const int nk = K / 16;
    for (int kt = 0; kt < nk; kt++) {
        const int p = kt & 1;
        if (kt + 1 < nk) {
            ra = *(const float4*)&A[(size_t)(m0 + r) * K + (kt + 1) * 16 + c];
            rw = *(const float4*)&W[(size_t)(n0 + r) * K + (kt + 1) * 16 + c];
        }
        const uint32_t off = base + (uint32_t)p * 128 * 48;
        uint32_t af[4], bt[2][4];
        ldsm4(af, off + (uint32_t)(wm * 16 + lr) * 48 + lb);
#pragma unroll
        for (int nt = 0; nt < 2; nt++)
            ldsm4(bt[nt], off + (uint32_t)(64 + wn * 32 + nt * 16 + lr) * 48 + lb);
#pragma unroll
        for (int ni = 0; ni < 4; ni++) {
            const int nt = ni >> 1, sub = ni & 1;
            mma16816(acc[ni], af, bt[nt][sub ? 1 : 0], bt[nt][sub ? 3 : 2]);
        }
        if (kt + 1 < nk) {
            __half* d = sm + (p ^ 1) * 128 * 24;
            sts16(d + r * 24 + c, ra);
            sts16(d + (64 + r) * 24 + c, rw);
        }
        __syncthreads();
    }

#pragma unroll
    for (int hf = 0; hf < 2; hf++) {
        const int row = m0 + wm * 16 + g + hf * 8;
#pragma unroll
        for (int ni = 0; ni < 4; ni++) {
            const int col = n0 + wn * 32 + ni * 8 + tg * 2;
            float2 o;
            o.x = acc[ni][hf * 2 + 0] + bias[col];
            o.y = acc[ni][hf * 2 + 1] + bias[col + 1];
            *(float2*)&C[(size_t)row * N + col] = o;
        }
    }
}

// ---------------- fused GRU layer kernel ----------------
// Per CTA: rows [by*64, +64), h-cols [bx*32, +32), all 3 gates, both GEMMs,
// gate nonlinearity fused in epilogue. KI = input width (768 layer0, 512 else).
// smem rows: 0..63 Ai | 64..127 Ah | 128..223 Wi(3x32) | 224..319 Wh(3x32)
template<int KI>
__global__ void __launch_bounds__(256, 2) gru_fused_kernel(
    const float* __restrict__ Ai, const float* __restrict__ Wi,
    const float* __restrict__ Ah, const float* __restrict__ Whh,
    const float* __restrict__ bi, const float* __restrict__ bh,
    float* __restrict__ hout) {
    __shared__ __align__(16) __half sm[2 * 320 * 24];

    const int tid = threadIdx.x;
    const int lane = tid & 31, wid = tid >> 5;
    const int wm = wid >> 1, wn = wid & 1;       // 4m x 2n, warp 16 rows x 16 cols
    const int g = lane >> 2, tg = lane & 3;
    const int lr = (lane & 7) + ((lane >> 3) & 1) * 8;
    const int lb = ((lane >> 4) & 1) * 16;
    const int m0 = blockIdx.y * 64;
    const int nb = blockIdx.x * 32;
    const uint32_t base = smem_u32(sm);

    const int r = tid >> 2, c = (tid & 3) * 4;
    float acc_i[3][2][4] = {};
    float acc_h[3][2][4] = {};

    float4 rai, rah, rwi0, rwi1, rwh0, rwh1;
    const int q0 = tid >> 2;                 // Wi/Wh rows 0..63
    const int q1 = 64 + (tid >> 2);          // rows 64..95 (tid<128)
    const int g0 = q0 >> 5, w0 = q0 & 31;
    const int g1 = q1 >> 5, w1 = q1 & 31;
    const bool has1 = (tid < 128);

    // prologue kt=0
    rai = *(const float4*)&Ai[(size_t)(m0 + r) * KI + c];
    rah = *(const float4*)&Ah[(size_t)(m0 + r) * H_ + c];
    rwi0 = *(const float4*)&Wi[(size_t)(g0 * H_ + nb + w0) * KI + c];
    rwh0 = *(const float4*)&Whh[(size_t)(g0 * H_ + nb + w0) * H_ + c];
    if (has1) {
        rwi1 = *(const float4*)&Wi[(size_t)(g1 * H_ + nb + w1) * KI + c];
        rwh1 = *(const float4*)&Whh[(size_t)(g1 * H_ + nb + w1) * H_ + c];
    }
    {
        __half* d = sm;
        sts16(d + r * 24 + c, rai);
        sts16(d + (64 + r) * 24 + c, rah);
        sts16(d + (128 + q0) * 24 + c, rwi0);
        sts16(d + (224 + q0) * 24 + c, rwh0);
        if (has1) {
            sts16(d + (128 + q1) * 24 + c, rwi1);
            sts16(d + (224 + q1) * 24 + c, rwh1);
        }
    }
    __syncthreads();

    constexpr int NKT = KI / 16;
    for (int kt = 0; kt < NKT; kt++) {
        const int p = kt & 1;
        const bool nxt = (kt + 1 < NKT);
        const bool nxt_h = (kt + 1 < 32);
        if (nxt) {
            rai = *(const float4*)&Ai[(size_t)(m0 + r) * KI + (kt + 1) * 16 + c];
            rwi0 = *(const float4*)&Wi[(size_t)(g0 * H_ + nb + w0) * KI + (kt + 1) * 16 + c];
            if (has1) rwi1 = *(const float4*)&Wi[(size_t)(g1 * H_ + nb + w1) * KI + (kt + 1) * 16 + c];
            if (nxt_h) {
                rah = *(const float4*)&Ah[(size_t)(m0 + r) * H_ + (kt + 1) * 16 + c];
                rwh0 = *(const float4*)&Whh[(size_t)(g0 * H_ + nb + w0) * H_ + (kt + 1) * 16 + c];
                if (has1) rwh1 = *(const float4*)&Whh[(size_t)(g1 * H_ + nb + w1) * H_ + (kt + 1) * 16 + c];
            }
        }
        const uint32_t off = base + (uint32_t)p * 320 * 48;
        uint32_t afi[4], afh[4], bwi[3][4], bwh[3][4];
        ldsm4(afi, off + (uint32_t)(wm * 16 + lr) * 48 + lb);
#pragma unroll
        for (int gt = 0; gt < 3; gt++)
            ldsm4(bwi[gt], off + (uint32_t)(128 + gt * 32 + wn * 16 + lr) * 48 + lb);
        const bool act_h = (kt < 32);
        if (act_h) {
            ldsm4(afh, off + (uint32_t)(64 + wm * 16 + lr) * 48 + lb);
#pragma unroll
            for (int gt = 0; gt < 3; gt++)
                ldsm4(bwh[gt], off + (uint32_t)(224 + gt * 32 + wn * 16 + lr) * 48 + lb);
        }
#pragma unroll
        for (int gt = 0; gt < 3; gt++)
#pragma unroll
            for (int sub = 0; sub < 2; sub++)
                mma16816(acc_i[gt][sub], afi, bwi[gt][sub], bwi[gt][sub + 2]);
        if (act_h) {
#pragma unroll
            for (int gt = 0; gt < 3; gt++)
#pragma unroll
                for (int sub = 0; sub < 2; sub++)
                    mma16816(acc_h[gt][sub], afh, bwh[gt][sub], bwh[gt][sub + 2]);
        }
        if (nxt) {
            __half* d = sm + (p ^ 1) * 320 * 24;
            sts16(d + r * 24 + c, rai);
            sts16(d + (128 + q0) * 24 + c, rwi0);
            if (has1) sts16(d + (128 + q1) * 24 + c, rwi1);
            if (nxt_h) {
                sts16(d + (64 + r) * 24 + c, rah);
                sts16(d + (224 + q0) * 24 + c, rwh0);
                if (has1) sts16(d + (224 + q1) * 24 + c, rwh1);
            }
        }
        __syncthreads();
    }

    // epilogue: gate nonlinearity, h update
#pragma unroll
    for (int hf = 0; hf < 2; hf++) {
        const int row = m0 + wm * 16 + g + hf * 8;
#pragma unroll
        for (int sub = 0; sub < 2; sub++) {
            const int col = nb + wn * 16 + sub * 8 + tg * 2;
            float2 hp = *(const float2*)&Ah[(size_t)row * H_ + col];
            float2 o;
#pragma unroll
            for (int j = 0; j < 2; j++) {
                const int cj = col + j;
                float ir = acc_i[0][sub][hf * 2 + j] + bi[cj];
                float hr = acc_h[0][sub][hf * 2 + j] + bh[cj];
                float iz = acc_i[1][sub][hf * 2 + j] + bi[H_ + cj];
                float hz = acc_h[1][sub][hf * 2 + j] + bh[H_ + cj];
                float in_ = acc_i[2][sub][hf * 2 + j] + bi[2 * H_ + cj];
                float hn = acc_h[2][sub][hf * 2 + j] + bh[2 * H_ + cj];
                float rr = sigf(ir + hr);
                float zz = sigf(iz + hz);
                float nn = tanhf(fmaf(rr, hn, in_));
                float hv = j ? hp.y : hp.x;
                float res = fmaf(zz, hv - nn, nn);
                if (j) o.y = res; else o.x = res;
            }
            *(float2*)&hout[(size_t)row * H_ + col] = o;
        }
    }
}

// ---------------- fused softmax + context + embedding ----------------
__global__ void __launch_bounds__(256) attn_ctx_kernel(
    const float* __restrict__ energy, const float* __restrict__ Es,
    const int* __restrict__ x, const float* __restrict__ emb,
    float* __restrict__ rnn) {
    __shared__ float red[S_];
    __shared__ float att[S_];
    const int b = blockIdx.x;
    const int s = threadIdx.x;

    float v = energy[s * B_ + b];
    red[s] = v;
    __syncthreads();
    for (int off = S_ / 2; off; off >>= 1) {
        if (s < off) red[s] = fmaxf(red[s], red[s + off]);
        __syncthreads();
    }
    float m = red[0];
    __syncthreads();
    float ex = __expf(v - m);
    red[s] = ex;
    __syncthreads();
    for (int off = S_ / 2; off; off >>= 1) {
        if (s < off) red[s] += red[s + off];
        __syncthreads();
    }
    att[s] = ex / red[0];
    __syncthreads();

    const int h = s * 2;
    float cx = 0.f, cy = 0.f;
    const float* base = Es + (size_t)b * H_ + h;
#pragma unroll 4
    for (int s2 = 0; s2 < S_; s2++) {
        float a = att[s2];
        float2 e = *(const float2*)&base[(size_t)s2 * B_ * H_];
        cx = fmaf(a, e.x, cx);
        cy = fmaf(a, e.y, cy);
    }
    *(float2*)&rnn[(size_t)b * (H_ + E_) + h] = make_float2(cx, cy);

    rnn[(size_t)b * (H_ + E_) + H_ + s] = emb[(size_t)x[b] * E_ + s];
}

// ---------------- launch ----------------
extern "C" void kernel_launch(void* const* d_in, const int* in_sizes, int n_in,
                              void* d_out, int out_size) {
    const int*   x      = (const int*)  d_in[0];
    const float* Es     = (const float*)d_in[1];
    const float* hidden = (const float*)d_in[2];
    const float* emb    = (const float*)d_in[4];
    const float* Uw     = (const float*)d_in[5];
    const float* Ub     = (const float*)d_in[6];
    const float* Ww     = (const float*)d_in[7];
    const float* Wb     = (const float*)d_in[8];
    const float* aw     = (const float*)d_in[9];
    const float* ab     = (const float*)d_in[10];
    const float* w_ih0  = (const float*)d_in[11];
    const float* w_hh0  = (const float*)d_in[12];
    const float* b_ih0  = (const float*)d_in[13];
    const float* b_hh0  = (const float*)d_in[14];
    const float* w_ih_r = (const float*)d_in[15];
    const float* w_hh_r = (const float*)d_in[16];
    const float* b_ih_r = (const float*)d_in[17];
    const float* b_hh_r = (const float*)d_in[18];
    const float* fcw    = (const float*)d_in[19];
    const float* fcb    = (const float*)d_in[20];

    float* out     = (float*)d_out;
    float* pred    = out;               // [B, OUT]
    float* hid_out = out + B_ * OUT_;   // [L, B, H]

    float *Wh, *rnn, *energy;
    cudaGetSymbolAddress((void**)&Wh,     g_Wh);
    cudaGetSymbolAddress((void**)&rnn,    g_rnn);
    cudaGetSymbolAddress((void**)&energy, g_energy);

    const float* hlast = hidden + (size_t)(L_ - 1) * B_ * H_;

    // 1) Wh = hidden[-1] @ Ww^T + Wb
    sgemm64_kernel<<<dim3(H_ / 64, B_ / 64), 256>>>(hlast, Ww, Wb, Wh, H_, H_);

    // 2) fused energy
    energy_hmma_kernel<<<(S_ * B_) / 128, 512>>>(Es, Uw, Ub, Wh, aw, ab, energy);

    // 3) softmax + context + embedding
    attn_ctx_kernel<<<B_, 256>>>(energy, Es, x, emb, rnn);

    // 4) fused GRU layers
    gru_fused_kernel<768><<<dim3(H_ / 32, B_ / 64), 256>>>(
        rnn, w_ih0, hidden, w_hh0, b_ih0, b_hh0, hid_out);
    for (int l = 1; l < L_; l++) {
        gru_fused_kernel<512><<<dim3(H_ / 32, B_ / 64), 256>>>(
            hid_out + (size_t)(l - 1) * B_ * H_,
            w_ih_r + (size_t)(l - 1) * 3 * H_ * H_,
            hidden + (size_t)l * B_ * H_,
            w_hh_r + (size_t)(l - 1) * 3 * H_ * H_,
            b_ih_r + (size_t)(l - 1) * 3 * H_,
            b_hh_r + (size_t)(l - 1) * 3 * H_,
            hid_out + (size_t)l * B_ * H_);
    }

    // 5) predictions = h_last @ fcw^T + fcb
    sgemm64_kernel<<<dim3(OUT_ / 64, B_ / 64), 256>>>(
        hid_out + (size_t)(L_ - 1) * B_ * H_, fcw, fcb, pred, H_, OUT_);
}